// round 14
// baseline (speedup 1.0000x reference)
#include <cuda_runtime.h>
#include <cstdint>

// Problem constants
#define NN 32
#define TT 1024
#define EE 64
#define HH 8
#define DD 8

// Attention kernel tiling
#define A_THREADS 128
#define QPT 4                       // q rows per thread
#define QROWS (A_THREADS * QPT)     // 512 q rows per CTA
#define QSPLIT (TT / QROWS)         // 2
#define KCHUNK 512                  // keys per smem stage (2 stages)

// Scratch for per-head attention output [N,T,E] (allocation-free: device global)
__device__ float g_heads[(size_t)NN * TT * EE];

typedef unsigned long long u64;

// ---- packed f32x2 helpers (sm_100+) ----
__device__ __forceinline__ u64 fma2(u64 a, u64 b, u64 c) {
    u64 d;
    asm("fma.rn.f32x2 %0, %1, %2, %3;" : "=l"(d) : "l"(a), "l"(b), "l"(c));
    return d;
}
__device__ __forceinline__ u64 mul2(u64 a, u64 b) {
    u64 d;
    asm("mul.rn.f32x2 %0, %1, %2;" : "=l"(d) : "l"(a), "l"(b));
    return d;
}
__device__ __forceinline__ u64 pack2(float lo, float hi) {
    u64 d;
    asm("mov.b64 %0, {%1, %2};" : "=l"(d)
        : "r"(__float_as_uint(lo)), "r"(__float_as_uint(hi)));
    return d;
}
__device__ __forceinline__ void unpack2(u64 a, float& lo, float& hi) {
    unsigned int l, h;
    asm("mov.b64 {%0, %1}, %2;" : "=r"(l), "=r"(h) : "l"(a));
    lo = __uint_as_float(l);
    hi = __uint_as_float(h);
}
__device__ __forceinline__ float hadd2(u64 a) {
    float lo, hi;
    unpack2(a, lo, hi);
    return lo + hi;
}

// ============================================================================
// Kernel A: fused projections (Wq,Wk,Wv) + single-pass softmax attention.
// grid = (QSPLIT, H, N), block = 128 threads.
// Each CTA: one (n,h), q rows [qs*512, qs*512+512). K/V projected into SMEM
// in 2 chunks of 512 keys; each thread owns 4 q rows with packed-f32x2
// accumulators. exp() is safe without max-subtraction because scores are
// clipped to [-5,5] (matching the reference exactly).
// ============================================================================
__global__ void __launch_bounds__(A_THREADS)
attn_kernel(const float* __restrict__ values,
            const float* __restrict__ keys,
            const float* __restrict__ query,
            const float* __restrict__ Wv,
            const float* __restrict__ Wk,
            const float* __restrict__ Wq)
{
    __shared__ __align__(16) float sK[KCHUNK * DD];   // 16 KB
    __shared__ __align__(16) float sV[KCHUNK * DD];   // 16 KB
    __shared__ float sWk[64], sWv[64], sWq[64];

    const int tid = threadIdx.x;
    const int qs  = blockIdx.x;
    const int h   = blockIdx.y;
    const int n   = blockIdx.z;

    if (tid < 64) {
        sWk[tid] = Wk[tid];
        sWv[tid] = Wv[tid];
        sWq[tid] = Wq[tid];
    }
    __syncthreads();

    // ---- load + project this thread's QPT q rows into packed registers ----
    u64 q2[QPT][4];
    int qrow[QPT];
#pragma unroll
    for (int r = 0; r < QPT; r++) {
        qrow[r] = qs * QROWS + r * A_THREADS + tid;
        const float4* qp = reinterpret_cast<const float4*>(
            query + ((size_t)(n * TT + qrow[r])) * EE + h * DD);
        float4 a = qp[0], b = qp[1];
        float in[8] = {a.x, a.y, a.z, a.w, b.x, b.y, b.z, b.w};
        float pr[8];
#pragma unroll
        for (int o = 0; o < 8; o++) {
            float s = 0.f;
#pragma unroll
            for (int i = 0; i < 8; i++) s += in[i] * sWq[o * 8 + i];
            pr[o] = s;
        }
#pragma unroll
        for (int p = 0; p < 4; p++) q2[r][p] = pack2(pr[2 * p], pr[2 * p + 1]);
    }

    u64 acc[QPT][4];
    float esum[QPT];
#pragma unroll
    for (int r = 0; r < QPT; r++) {
        esum[r] = 0.f;
#pragma unroll
        for (int p = 0; p < 4; p++) acc[r][p] = 0ull;
    }

    const float scale = 0.125f;  // 1/sqrt(E=64)

    for (int kc = 0; kc < TT; kc += KCHUNK) {
        // ---- project K,V chunk into SMEM ----
        for (int t = tid; t < KCHUNK; t += A_THREADS) {
            const int row = kc + t;
            {
                const float4* kp = reinterpret_cast<const float4*>(
                    keys + ((size_t)(n * TT + row)) * EE + h * DD);
                float4 a = kp[0], b = kp[1];
                float in[8] = {a.x, a.y, a.z, a.w, b.x, b.y, b.z, b.w};
                float pr[8];
#pragma unroll
                for (int o = 0; o < 8; o++) {
                    float s = 0.f;
#pragma unroll
                    for (int i = 0; i < 8; i++) s += in[i] * sWk[o * 8 + i];
                    pr[o] = s;
                }
                *reinterpret_cast<float4*>(sK + t * 8) =
                    make_float4(pr[0], pr[1], pr[2], pr[3]);
                *reinterpret_cast<float4*>(sK + t * 8 + 4) =
                    make_float4(pr[4], pr[5], pr[6], pr[7]);
            }
            {
                const float4* vp = reinterpret_cast<const float4*>(
                    values + ((size_t)(n * TT + row)) * EE + h * DD);
                float4 a = vp[0], b = vp[1];
                float in[8] = {a.x, a.y, a.z, a.w, b.x, b.y, b.z, b.w};
                float pr[8];
#pragma unroll
                for (int o = 0; o < 8; o++) {
                    float s = 0.f;
#pragma unroll
                    for (int i = 0; i < 8; i++) s += in[i] * sWv[o * 8 + i];
                    pr[o] = s;
                }
                *reinterpret_cast<float4*>(sV + t * 8) =
                    make_float4(pr[0], pr[1], pr[2], pr[3]);
                *reinterpret_cast<float4*>(sV + t * 8 + 4) =
                    make_float4(pr[4], pr[5], pr[6], pr[7]);
            }
        }
        __syncthreads();

        // ---- stream keys: score -> clip -> exp -> accumulate (single pass) ----
#pragma unroll 2
        for (int j = 0; j < KCHUNK; j++) {
            const ulonglong2 kA = *reinterpret_cast<const ulonglong2*>(sK + j * 8);
            const ulonglong2 kB = *reinterpret_cast<const ulonglong2*>(sK + j * 8 + 4);
            const ulonglong2 vA = *reinterpret_cast<const ulonglong2*>(sV + j * 8);
            const ulonglong2 vB = *reinterpret_cast<const ulonglong2*>(sV + j * 8 + 4);
#pragma unroll
            for (int r = 0; r < QPT; r++) {
                u64 d = mul2(q2[r][0], kA.x);
                d = fma2(q2[r][1], kA.y, d);
                d = fma2(q2[r][2], kB.x, d);
                d = fma2(q2[r][3], kB.y, d);
                float s = hadd2(d) * scale;
                s = fminf(fmaxf(s, -5.f), 5.f);
                float e = __expf(s);
                esum[r] += e;
                u64 e2 = pack2(e, e);
                acc[r][0] = fma2(e2, vA.x, acc[r][0]);
                acc[r][1] = fma2(e2, vA.y, acc[r][1]);
                acc[r][2] = fma2(e2, vB.x, acc[r][2]);
                acc[r][3] = fma2(e2, vB.y, acc[r][3]);
            }
        }
        __syncthreads();
    }

    // ---- normalize and write per-head output into scratch [N,T,E] ----
#pragma unroll
    for (int r = 0; r < QPT; r++) {
        const float inv = 1.f / esum[r];
        float o[8];
#pragma unroll
        for (int p = 0; p < 4; p++) {
            float lo, hi;
            unpack2(acc[r][p], lo, hi);
            o[2 * p]     = lo * inv;
            o[2 * p + 1] = hi * inv;
        }
        float* dst = g_heads + ((size_t)(n * TT + qrow[r])) * EE + h * DD;
        *reinterpret_cast<float4*>(dst)     = make_float4(o[0], o[1], o[2], o[3]);
        *reinterpret_cast<float4*>(dst + 4) = make_float4(o[4], o[5], o[6], o[7]);
    }
}

// ============================================================================
// Kernel B: output projection  out = heads @ Wo^T + bo   (64x64 per token).
// Wo stored TRANSPOSED in SMEM so the inner loop reads consecutive addresses
// (conflict-free) instead of 32-way-conflicting rows.
// block = 128 threads -> 8 tokens/block, each thread computes 4 outputs.
// ============================================================================
#define B_TPB 8  // tokens per block

__global__ void __launch_bounds__(128)
proj_kernel(const float* __restrict__ Wo,
            const float* __restrict__ bo,
            float* __restrict__ out)
{
    __shared__ __align__(16) float sWoT[64 * 64];  // [i][o], 16 KB
    __shared__ __align__(16) float sx[B_TPB * 64];
    __shared__ float sbo[64];

    const int tid = threadIdx.x;
    const int tok0 = blockIdx.x * B_TPB;

    // Wo transposed into SMEM
    for (int idx = tid; idx < 64 * 64; idx += 128) {
        int o = idx >> 6, i = idx & 63;
        sWoT[i * 64 + o] = Wo[idx];
    }
    if (tid < 64) sbo[tid] = bo[tid];

    // 8 tokens x 64 floats = 128 float4 -> one per thread
    reinterpret_cast<float4*>(sx)[tid] =
        reinterpret_cast<const float4*>(g_heads + (size_t)tok0 * 64)[tid];
    __syncthreads();

    const int og = (tid & 15) * 4;  // output group of 4
    const int ts = tid >> 4;        // token slot 0..7

    float a0 = sbo[og + 0], a1 = sbo[og + 1], a2 = sbo[og + 2], a3 = sbo[og + 3];
#pragma unroll
    for (int i = 0; i < 64; i++) {
        const float xv = sx[ts * 64 + i];
        const float4 w = *reinterpret_cast<const float4*>(sWoT + i * 64 + og);
        a0 += xv * w.x;
        a1 += xv * w.y;
        a2 += xv * w.z;
        a3 += xv * w.w;
    }
    *reinterpret_cast<float4*>(out + (size_t)(tok0 + ts) * 64 + og) =
        make_float4(a0, a1, a2, a3);
}

// ============================================================================
// Launch
// ============================================================================
extern "C" void kernel_launch(void* const* d_in, const int* in_sizes, int n_in,
                              void* d_out, int out_size)
{
    const float* values = (const float*)d_in[0];
    const float* keys   = (const float*)d_in[1];
    const float* query  = (const float*)d_in[2];
    const float* Wv     = (const float*)d_in[3];
    const float* Wk     = (const float*)d_in[4];
    const float* Wq     = (const float*)d_in[5];
    const float* Wo     = (const float*)d_in[6];
    const float* bo     = (const float*)d_in[7];
    float* out = (float*)d_out;

    dim3 gridA(QSPLIT, HH, NN);  // (2, 8, 32) = 512 CTAs
    attn_kernel<<<gridA, A_THREADS>>>(values, keys, query, Wv, Wk, Wq);

    const int n_tokens = NN * TT;  // 32768
    proj_kernel<<<n_tokens / B_TPB, 128>>>(Wo, bo, out);
}

// round 15
// speedup vs baseline: 1.3074x; 1.3074x over previous
#include <cuda_runtime.h>
#include <cstdint>

// Problem constants
#define NN 32
#define TT 1024
#define EE 64
#define HH 8
#define DD 8

// Attention tiling
#define A_THREADS 128
#define QPT 4
#define QROWS (A_THREADS * QPT)   // 512
#define QSPLIT (TT / QROWS)       // 2
#define KCHUNK 512

#define LOG2E 1.4426950408889634f
#define QSCALE (0.125f * LOG2E)   // 1/sqrt(64) * log2(e), folded into q
#define CLIPV (5.0f * LOG2E)      // clip(energy*scale, ±5) in log2 domain

// Device scratch (allocation-free)
__device__ float g_q[(size_t)NN * HH * TT * DD];   // prescaled projected Q [n,h,t,d]
__device__ float g_k[(size_t)NN * HH * TT * DD];
__device__ float g_v[(size_t)NN * HH * TT * DD];
__device__ float g_heads[(size_t)NN * TT * EE];    // attention output [n,t,e]

typedef unsigned long long u64;

// ---- packed f32x2 helpers ----
__device__ __forceinline__ u64 fma2(u64 a, u64 b, u64 c) {
    u64 d; asm("fma.rn.f32x2 %0, %1, %2, %3;" : "=l"(d) : "l"(a), "l"(b), "l"(c));
    return d;
}
__device__ __forceinline__ u64 mul2(u64 a, u64 b) {
    u64 d; asm("mul.rn.f32x2 %0, %1, %2;" : "=l"(d) : "l"(a), "l"(b));
    return d;
}
__device__ __forceinline__ u64 pack2(float lo, float hi) {
    u64 d; asm("mov.b64 %0, {%1, %2};" : "=l"(d)
               : "r"(__float_as_uint(lo)), "r"(__float_as_uint(hi)));
    return d;
}
__device__ __forceinline__ void unpack2(u64 a, float& lo, float& hi) {
    unsigned int l, h;
    asm("mov.b64 {%0, %1}, %2;" : "=r"(l), "=r"(h) : "l"(a));
    lo = __uint_as_float(l); hi = __uint_as_float(h);
}
__device__ __forceinline__ float hadd2(u64 a) {
    float lo, hi; unpack2(a, lo, hi); return lo + hi;
}
__device__ __forceinline__ float ex2f(float x) {
    float r; asm("ex2.approx.ftz.f32 %0, %1;" : "=f"(r) : "f"(x));
    return r;
}

// ============================================================================
// Kernel 0: QKV projection. thread = (token, head), h fastest (coalesced read).
// q is pre-scaled by QSCALE so the attention score is already in ex2 domain.
// Output layout [n,h,t,d] so attention chunk fills are contiguous bulk copies.
// ============================================================================
__global__ void __launch_bounds__(256)
qkv_kernel(const float* __restrict__ values,
           const float* __restrict__ keys,
           const float* __restrict__ query,
           const float* __restrict__ Wv,
           const float* __restrict__ Wk,
           const float* __restrict__ Wq)
{
    __shared__ float sWv[64], sWk[64], sWq[64];
    const int tid = threadIdx.x;
    if (tid < 64) { sWv[tid] = Wv[tid]; sWk[tid] = Wk[tid]; sWq[tid] = Wq[tid]; }
    __syncthreads();

    const int id  = blockIdx.x * 256 + tid;     // 0 .. 262143
    const int tok = id >> 3;                    // n*T + t
    const int h   = id & 7;
    const int n   = tok >> 10;
    const int t   = tok & 1023;
    const size_t src = (size_t)tok * EE + h * DD;
    const size_t dst = ((size_t)(n * HH + h) * TT + t) * DD;

    float in[8], pr[8];

    // Q (pre-scaled)
    {
        float4 a = *(const float4*)(query + src);
        float4 b = *(const float4*)(query + src + 4);
        in[0]=a.x; in[1]=a.y; in[2]=a.z; in[3]=a.w;
        in[4]=b.x; in[5]=b.y; in[6]=b.z; in[7]=b.w;
#pragma unroll
        for (int o = 0; o < 8; o++) {
            float s = 0.f;
#pragma unroll
            for (int i = 0; i < 8; i++) s += in[i] * sWq[o * 8 + i];
            pr[o] = s * QSCALE;
        }
        *(float4*)(g_q + dst)     = make_float4(pr[0], pr[1], pr[2], pr[3]);
        *(float4*)(g_q + dst + 4) = make_float4(pr[4], pr[5], pr[6], pr[7]);
    }
    // K
    {
        float4 a = *(const float4*)(keys + src);
        float4 b = *(const float4*)(keys + src + 4);
        in[0]=a.x; in[1]=a.y; in[2]=a.z; in[3]=a.w;
        in[4]=b.x; in[5]=b.y; in[6]=b.z; in[7]=b.w;
#pragma unroll
        for (int o = 0; o < 8; o++) {
            float s = 0.f;
#pragma unroll
            for (int i = 0; i < 8; i++) s += in[i] * sWk[o * 8 + i];
            pr[o] = s;
        }
        *(float4*)(g_k + dst)     = make_float4(pr[0], pr[1], pr[2], pr[3]);
        *(float4*)(g_k + dst + 4) = make_float4(pr[4], pr[5], pr[6], pr[7]);
    }
    // V
    {
        float4 a = *(const float4*)(values + src);
        float4 b = *(const float4*)(values + src + 4);
        in[0]=a.x; in[1]=a.y; in[2]=a.z; in[3]=a.w;
        in[4]=b.x; in[5]=b.y; in[6]=b.z; in[7]=b.w;
#pragma unroll
        for (int o = 0; o < 8; o++) {
            float s = 0.f;
#pragma unroll
            for (int i = 0; i < 8; i++) s += in[i] * sWv[o * 8 + i];
            pr[o] = s;
        }
        *(float4*)(g_v + dst)     = make_float4(pr[0], pr[1], pr[2], pr[3]);
        *(float4*)(g_v + dst + 4) = make_float4(pr[4], pr[5], pr[6], pr[7]);
    }
}

// ============================================================================
// Kernel A: single-pass softmax attention on projected tensors.
// scores are already in log2 domain (q prescaled); exp = raw ex2.approx.
// Clip at ±5*log2e matches the reference's clip(energy*scale, ±5).
// ============================================================================
__global__ void __launch_bounds__(A_THREADS)
attn_kernel()
{
    __shared__ __align__(16) float sK[KCHUNK * DD];  // 16 KB
    __shared__ __align__(16) float sV[KCHUNK * DD];  // 16 KB

    const int tid = threadIdx.x;
    const int qs  = blockIdx.x;
    const int h   = blockIdx.y;
    const int n   = blockIdx.z;

    const size_t base = (size_t)(n * HH + h) * TT * DD;

    // load QPT prescaled q rows (packed f32x2 over dims)
    u64 q2[QPT][4];
    int qrow[QPT];
#pragma unroll
    for (int r = 0; r < QPT; r++) {
        qrow[r] = qs * QROWS + r * A_THREADS + tid;
        const ulonglong2* qp =
            reinterpret_cast<const ulonglong2*>(g_q + base + (size_t)qrow[r] * DD);
        ulonglong2 a = qp[0], b = qp[1];
        q2[r][0] = a.x; q2[r][1] = a.y; q2[r][2] = b.x; q2[r][3] = b.y;
    }

    u64 acc[QPT][4];
    float esum[QPT];
#pragma unroll
    for (int r = 0; r < QPT; r++) {
        esum[r] = 0.f;
#pragma unroll
        for (int p = 0; p < 4; p++) acc[r][p] = 0ull;
    }

    for (int kc = 0; kc < TT; kc += KCHUNK) {
        // bulk copy projected K/V chunk into smem (contiguous, coalesced)
        const float4* kb = reinterpret_cast<const float4*>(g_k + base + (size_t)kc * DD);
        const float4* vb = reinterpret_cast<const float4*>(g_v + base + (size_t)kc * DD);
#pragma unroll
        for (int t = 0; t < (KCHUNK * DD / 4) / A_THREADS; t++) {
            const int idx = t * A_THREADS + tid;
            reinterpret_cast<float4*>(sK)[idx] = kb[idx];
            reinterpret_cast<float4*>(sV)[idx] = vb[idx];
        }
        __syncthreads();

#pragma unroll 4
        for (int j = 0; j < KCHUNK; j++) {
            const ulonglong2 kA = *reinterpret_cast<const ulonglong2*>(sK + j * 8);
            const ulonglong2 kB = *reinterpret_cast<const ulonglong2*>(sK + j * 8 + 4);
            const ulonglong2 vA = *reinterpret_cast<const ulonglong2*>(sV + j * 8);
            const ulonglong2 vB = *reinterpret_cast<const ulonglong2*>(sV + j * 8 + 4);
#pragma unroll
            for (int r = 0; r < QPT; r++) {
                u64 d = mul2(q2[r][0], kA.x);
                d = fma2(q2[r][1], kA.y, d);
                d = fma2(q2[r][2], kB.x, d);
                d = fma2(q2[r][3], kB.y, d);
                float s = hadd2(d);                    // already * scale*log2e
                s = fminf(fmaxf(s, -CLIPV), CLIPV);    // clip(±5) in log2 domain
                float e = ex2f(s);
                esum[r] += e;
                u64 e2 = pack2(e, e);
                acc[r][0] = fma2(e2, vA.x, acc[r][0]);
                acc[r][1] = fma2(e2, vA.y, acc[r][1]);
                acc[r][2] = fma2(e2, vB.x, acc[r][2]);
                acc[r][3] = fma2(e2, vB.y, acc[r][3]);
            }
        }
        __syncthreads();
    }

    // normalize + write per-head output [n,t,e]
#pragma unroll
    for (int r = 0; r < QPT; r++) {
        const float inv = 1.f / esum[r];
        float o[8];
#pragma unroll
        for (int p = 0; p < 4; p++) {
            float lo, hi; unpack2(acc[r][p], lo, hi);
            o[2 * p] = lo * inv; o[2 * p + 1] = hi * inv;
        }
        float* dst = g_heads + ((size_t)(n * TT + qrow[r])) * EE + h * DD;
        *(float4*)(dst)     = make_float4(o[0], o[1], o[2], o[3]);
        *(float4*)(dst + 4) = make_float4(o[4], o[5], o[6], o[7]);
    }
}

// ============================================================================
// Kernel B: out = heads @ Wo^T + bo, with Wo held ENTIRELY in registers:
// each lane owns rows o=lane and o=lane+32 (64 regs each). Per token, x is
// staged in per-warp smem and read via broadcast LDS (1 wavefront each).
// 4 split accumulators break the FADD dependency chain.
// ============================================================================
#define PB_WARPS 8
#define PB_TOKS 8     // tokens per warp
#define PB_BLOCK (PB_WARPS * 32)

__global__ void __launch_bounds__(PB_BLOCK)
out_kernel(const float* __restrict__ Wo,
           const float* __restrict__ bo,
           float* __restrict__ out)
{
    __shared__ float sW[64 * 65];            // padded: bank-conflict-free row reads
    __shared__ float sx[PB_WARPS][64];
    __shared__ float sb[64];

    const int tid  = threadIdx.x;
    const int lane = tid & 31;
    const int warp = tid >> 5;

    for (int idx = tid; idx < 64 * 64; idx += PB_BLOCK) {
        int o = idx >> 6, i = idx & 63;
        sW[o * 65 + i] = Wo[idx];
    }
    if (tid < 64) sb[tid] = bo[tid];
    __syncthreads();

    // pull this lane's two Wo rows into registers (conflict-free: stride 65)
    float Wr0[64], Wr1[64];
#pragma unroll
    for (int i = 0; i < 64; i++) {
        Wr0[i] = sW[lane * 65 + i];
        Wr1[i] = sW[(lane + 32) * 65 + i];
    }
    const float b0 = sb[lane], b1 = sb[lane + 32];

    const int tok0 = blockIdx.x * (PB_WARPS * PB_TOKS) + warp * PB_TOKS;
    float* sxw = sx[warp];

    for (int t = 0; t < PB_TOKS; t++) {
        const int tok = tok0 + t;
        const float2 xv =
            *reinterpret_cast<const float2*>(g_heads + (size_t)tok * 64 + lane * 2);
        __syncwarp();
        *reinterpret_cast<float2*>(sxw + lane * 2) = xv;
        __syncwarp();

        float a0 = b0, a1 = b1, c0 = 0.f, c1 = 0.f;
#pragma unroll
        for (int i = 0; i < 64; i += 2) {
            const float x0 = sxw[i], x1 = sxw[i + 1];
            a0 += x0 * Wr0[i];     a1 += x0 * Wr1[i];
            c0 += x1 * Wr0[i + 1]; c1 += x1 * Wr1[i + 1];
        }
        out[(size_t)tok * 64 + lane]      = a0 + c0;
        out[(size_t)tok * 64 + 32 + lane] = a1 + c1;
    }
}

// ============================================================================
// Launch
// ============================================================================
extern "C" void kernel_launch(void* const* d_in, const int* in_sizes, int n_in,
                              void* d_out, int out_size)
{
    const float* values = (const float*)d_in[0];
    const float* keys   = (const float*)d_in[1];
    const float* query  = (const float*)d_in[2];
    const float* Wv     = (const float*)d_in[3];
    const float* Wk     = (const float*)d_in[4];
    const float* Wq     = (const float*)d_in[5];
    const float* Wo     = (const float*)d_in[6];
    const float* bo     = (const float*)d_in[7];
    float* out = (float*)d_out;

    qkv_kernel<<<(NN * TT * HH) / 256, 256>>>(values, keys, query, Wv, Wk, Wq);

    dim3 gridA(QSPLIT, HH, NN);  // 512 CTAs
    attn_kernel<<<gridA, A_THREADS>>>();

    const int n_tokens = NN * TT;  // 32768
    out_kernel<<<n_tokens / (PB_WARPS * PB_TOKS), PB_BLOCK>>>(Wo, bo, out);
}